// round 13
// baseline (speedup 1.0000x reference)
#include <cuda_runtime.h>
#include <cstdint>

#define NN 2048
#define EE 65536
#define CC 32
#define TT 32               // edges per CTA tile
#define NTILES (EE / TT)    // 2048
#define GRID_EH 444         // 3 CTAs x 148 SMs

// Packed fp32x2 helpers (sm_103a FFMA2 path — only reachable via PTX)
#define PACK_F32X2(out, lo, hi) \
    asm("mov.b64 %0, {%1, %2};" : "=l"(out) : "f"(lo), "f"(hi))
#define UNPACK_F32X2(lo, hi, in) \
    asm("mov.b64 {%0, %1}, %2;" : "=f"(lo), "=f"(hi) : "l"(in))
#define FMA_F32X2(out, a, b, c) \
    asm("fma.rn.f32x2 %0, %1, %2, %3;" : "=l"(out) : "l"(a), "l"(b), "l"(c))
#define ADD_F32X2(out, a, b) \
    asm("add.rn.f32x2 %0, %1, %2;" : "=l"(out) : "l"(a), "l"(b))

// Scratch (device globals — no allocation allowed)
__device__ float g_agg1[NN * CC];
__device__ float g_agg2[NN * CC];
__device__ float g_agg3[NN * CC];
__device__ float g_cnt[NN];
__device__ float g_h1[NN * CC];
__device__ float g_h2[NN * CC];
__device__ float g_h3[NN * CC];

// ---------------------------------------------------------------------------
__global__ void zero_kernel() {
    int tid = blockIdx.x * blockDim.x + threadIdx.x;
    if (tid < NN * CC) {
        g_agg1[tid] = 0.f;
        g_agg2[tid] = 0.f;
        g_agg3[tid] = 0.f;
    }
    if (tid < NN) g_cnt[tid] = 0.f;
}

// ---------------------------------------------------------------------------
// Layer 1 edge pass (in_c = 1)
// ---------------------------------------------------------------------------
__global__ void edge1_kernel(const float* __restrict__ x,
                             const float* __restrict__ ea,
                             const int* __restrict__ src,
                             const int* __restrict__ dst,
                             const float* __restrict__ W1,
                             const float* __restrict__ b1) {
    int lane = threadIdx.x & 31;
    int warp = (blockIdx.x * blockDim.x + threadIdx.x) >> 5;
    int nw = (gridDim.x * blockDim.x) >> 5;

    float w[6];
#pragma unroll
    for (int v = 0; v < 6; v++) w[v] = W1[v * CC + lane];
    float bb = b1[lane];

    for (int e = warp; e < EE; e += nw) {
        int s = src[e];
        int d = dst[e];
        float acc = bb;
#pragma unroll
        for (int v = 0; v < 6; v++) acc = fmaf(ea[e * 6 + v], w[v], acc);
        acc = fmaxf(acc, 0.f);
        float msg = x[s] * acc;
        atomicAdd(&g_agg1[d * CC + lane], msg);
        if (lane == 0) atomicAdd(&g_cnt[d], 1.0f);
    }
}

// ---------------------------------------------------------------------------
__global__ void node1_kernel(const float* __restrict__ x,
                             const float* __restrict__ root1,
                             const float* __restrict__ bias1) {
    int tid = blockIdx.x * blockDim.x + threadIdx.x;
    if (tid >= NN * CC) return;
    int n = tid >> 5;
    int o = tid & 31;
    float inv = 1.0f / fmaxf(g_cnt[n], 1.0f);
    float v = g_agg1[tid] * inv + x[n] * root1[o] + bias1[o];
    g_h1[tid] = fmaxf(v, 0.f);
}

// ---------------------------------------------------------------------------
// Heavy edge pass: 8-WAY channel split (each warp owns 4 input channels),
// ~70 regs -> 3 CTAs/SM = 24 warps (6/SMSP). Staged 32-edge tiles,
// smem partial reduce -> 1 global RED per (edge,lane).
// ReLU deferred-x2 (0.5 folded into nodeH divisor).
// ---------------------------------------------------------------------------
__global__ void __launch_bounds__(256, 3)
edgeH_kernel(const float* __restrict__ h_in,
             const float* __restrict__ ea,
             const int* __restrict__ src,
             const int* __restrict__ dst,
             const float* __restrict__ W,
             const float* __restrict__ b,
             float* __restrict__ agg) {
    int lane = threadIdx.x & 31;
    int w = threadIdx.x >> 5;       // warp in CTA, 0..7 = channel octet
    int ibase = w << 2;             // 4 input channels per warp
    int tx = threadIdx.x;

    __shared__ __align__(16) uint64_t sh_ea[TT][6];   // dup (v,v) pairs, 48B rows
    __shared__ __align__(16) float sh_h[TT][36];      // padded gather staging
    __shared__ float sh_part[8 * TT * 32];            // octet partials [w][e][lane]

    // W slice packed: wr2[t][v] = (W[v,ibase+2t,lane], W[v,ibase+2t+1,lane])
    uint64_t wr2[2][6];
#pragma unroll
    for (int t = 0; t < 2; t++)
#pragma unroll
        for (int v = 0; v < 6; v++) {
            float lo = W[v * (CC * CC) + (ibase + 2 * t) * CC + lane];
            float hi = W[v * (CC * CC) + (ibase + 2 * t + 1) * CC + lane];
            PACK_F32X2(wr2[t][v], lo, hi);
        }
    uint64_t bb2[2];
#pragma unroll
    for (int t = 0; t < 2; t++) {
        float lo = b[(ibase + 2 * t) * CC + lane];
        float hi = b[(ibase + 2 * t + 1) * CC + lane];
        PACK_F32X2(bb2[t], lo, hi);
    }

    const float2* ea2 = (const float2*)ea;
    const uint64_t ABSMASK = 0x7FFFFFFF7FFFFFFFull;

    // staging roles
    int e_h = tx >> 3, qq = tx & 7;          // h: 8 threads/edge, 1 float4 each
    int e_a = tx / 3, k_a = tx - e_a * 3;    // ea: threads 0..95, 1 float2 each

    for (int tile = blockIdx.x; tile < NTILES; tile += GRID_EH) {
        int e0 = tile * TT;

        // ---- stage: ea (dup-packed) + bulk h gather ----
        if (tx < 96) {
            float2 v = __ldg(&ea2[(e0 + e_a) * 3 + k_a]);
            uint64_t p0, p1;
            PACK_F32X2(p0, v.x, v.x);
            PACK_F32X2(p1, v.y, v.y);
            sh_ea[e_a][2 * k_a] = p0;
            sh_ea[e_a][2 * k_a + 1] = p1;
        }
        {
            int s = __ldg(src + e0 + e_h);   // broadcast LDG (8 threads share)
            float4 hreg = __ldg((const float4*)(h_in + s * CC) + qq);
            *(float4*)&sh_h[e_h][qq * 4] = hreg;
        }
        __syncthreads();

        // ---- compute: every warp -> all 32 edges x its 4 input channels ----
#pragma unroll 4
        for (int e = 0; e < TT; ++e) {
            ulonglong2 eA = *(const ulonglong2*)&sh_ea[e][0];
            ulonglong2 eB = *(const ulonglong2*)&sh_ea[e][2];
            ulonglong2 eC = *(const ulonglong2*)&sh_ea[e][4];
            ulonglong2 hA = *(const ulonglong2*)&sh_h[e][ibase];  // 4 floats, 16B-aligned

            uint64_t mm0 = 0ull, mm1 = 0ull;
#pragma unroll
            for (int t = 0; t < 2; t++) {
                uint64_t acc = bb2[t];
                FMA_F32X2(acc, eA.x, wr2[t][0], acc);
                FMA_F32X2(acc, eA.y, wr2[t][1], acc);
                FMA_F32X2(acc, eB.x, wr2[t][2], acc);
                FMA_F32X2(acc, eB.y, wr2[t][3], acc);
                FMA_F32X2(acc, eC.x, wr2[t][4], acc);
                FMA_F32X2(acc, eC.y, wr2[t][5], acc);
                // 2*relu(acc) = acc + |acc| (0.5 folded into nodeH divisor)
                uint64_t accr;
                ADD_F32X2(accr, acc, acc & ABSMASK);
                if (t) { FMA_F32X2(mm1, hA.y, accr, mm1); }
                else   { FMA_F32X2(mm0, hA.x, accr, mm0); }
            }
            uint64_t msum;
            ADD_F32X2(msum, mm0, mm1);
            float p0, p1;
            UNPACK_F32X2(p0, p1, msum);
            sh_part[w * (TT * 32) + e * 32 + lane] = p0 + p1;   // conflict-free STS
        }
        __syncthreads();

        // ---- reduce octets + single global RED per (edge,lane) ----
#pragma unroll
        for (int k = 0; k < 4; k++) {
            int idx = k * 256 + tx;          // (edge,lane) flat in [0,1024)
            int e = idx >> 5, l = idx & 31;
            float v = ((sh_part[idx] + sh_part[TT * 32 + idx]) +
                       (sh_part[2 * TT * 32 + idx] + sh_part[3 * TT * 32 + idx])) +
                      ((sh_part[4 * TT * 32 + idx] + sh_part[5 * TT * 32 + idx]) +
                       (sh_part[6 * TT * 32 + idx] + sh_part[7 * TT * 32 + idx]));
            int d = __ldg(dst + e0 + e);     // broadcast LDG (32 threads share)
            atomicAdd(&agg[d * CC + l], v);
        }
        __syncthreads();   // protect smem before next tile
    }
}

// ---------------------------------------------------------------------------
// Heavy node pass. agg holds 2x the true message sum (deferred ReLU scale),
// so the mean divisor uses 0.5 (exact power-of-2 fold).
// ---------------------------------------------------------------------------
__global__ void nodeH_kernel(const float* __restrict__ h_in,
                             const float* __restrict__ agg,
                             const float* __restrict__ root,
                             const float* __restrict__ bias,
                             float* __restrict__ h_out) {
    int lane = threadIdx.x & 31;
    int warp = (blockIdx.x * blockDim.x + threadIdx.x) >> 5;
    if (warp >= NN) return;

    float r[CC];
#pragma unroll
    for (int i = 0; i < CC; i++) r[i] = root[i * CC + lane];

    float hv = h_in[warp * CC + lane];
    float a0 = bias[lane], a1 = 0.f, a2 = 0.f, a3 = 0.f;
#pragma unroll
    for (int i = 0; i < CC; i += 4) {
        a0 = fmaf(__shfl_sync(0xffffffffu, hv, i + 0), r[i + 0], a0);
        a1 = fmaf(__shfl_sync(0xffffffffu, hv, i + 1), r[i + 1], a1);
        a2 = fmaf(__shfl_sync(0xffffffffu, hv, i + 2), r[i + 2], a2);
        a3 = fmaf(__shfl_sync(0xffffffffu, hv, i + 3), r[i + 3], a3);
    }
    float inv = 0.5f / fmaxf(g_cnt[warp], 1.0f);   // 0.5: undo deferred ReLU scale
    float v = agg[warp * CC + lane] * inv + (a0 + a1) + (a2 + a3);
    h_out[warp * CC + lane] = fmaxf(v, 0.f);
}

// ---------------------------------------------------------------------------
// CBT: out[i,j] = sum_k |h3[j,k] - h3[i,k]|   (R8 scalar form — proven best)
// ---------------------------------------------------------------------------
__global__ void __launch_bounds__(128)
cbt_kernel(float* __restrict__ out) {
    __shared__ float si[32 * 33];
    __shared__ float sj[128 * 33];
    int tx = threadIdx.x;
    int j0 = blockIdx.x * 128;
    int i0 = blockIdx.y * 32;

    for (int t = tx; t < 32 * CC; t += 128) {
        int r = t >> 5, c = t & 31;
        si[r * 33 + c] = g_h3[(i0 + r) * CC + c];
    }
    for (int t = tx; t < 128 * CC; t += 128) {
        int r = t >> 5, c = t & 31;
        sj[r * 33 + c] = g_h3[(j0 + r) * CC + c];
    }
    __syncthreads();

    float hj[CC];
#pragma unroll
    for (int k = 0; k < CC; k++) hj[k] = sj[tx * 33 + k];

    for (int i = 0; i < 32; i++) {
        float s0 = 0.f, s1 = 0.f;
#pragma unroll
        for (int k = 0; k < CC; k += 2) {
            s0 += fabsf(si[i * 33 + k] - hj[k]);
            s1 += fabsf(si[i * 33 + k + 1] - hj[k + 1]);
        }
        out[(size_t)(i0 + i) * NN + j0 + tx] = s0 + s1;
    }
}

// ---------------------------------------------------------------------------
extern "C" void kernel_launch(void* const* d_in, const int* in_sizes, int n_in,
                              void* d_out, int out_size) {
    const float* x     = (const float*)d_in[0];
    const float* ea    = (const float*)d_in[1];
    const int*   ei    = (const int*)d_in[2];   // int32 (JAX x64 disabled)
    const float* W1    = (const float*)d_in[3];
    const float* b1    = (const float*)d_in[4];
    const float* root1 = (const float*)d_in[5];
    const float* bias1 = (const float*)d_in[6];
    const float* W2    = (const float*)d_in[7];
    const float* b2    = (const float*)d_in[8];
    const float* root2 = (const float*)d_in[9];
    const float* bias2 = (const float*)d_in[10];
    const float* W3    = (const float*)d_in[11];
    const float* b3    = (const float*)d_in[12];
    const float* root3 = (const float*)d_in[13];
    const float* bias3 = (const float*)d_in[14];
    float* out = (float*)d_out;

    const int* src = ei;
    const int* dst = ei + EE;

    float* agg1; float* agg2; float* agg3;
    float* h1;   float* h2;   float* h3;
    cudaGetSymbolAddress((void**)&agg1, g_agg1);
    cudaGetSymbolAddress((void**)&agg2, g_agg2);
    cudaGetSymbolAddress((void**)&agg3, g_agg3);
    cudaGetSymbolAddress((void**)&h1, g_h1);
    cudaGetSymbolAddress((void**)&h2, g_h2);
    cudaGetSymbolAddress((void**)&h3, g_h3);

    // 1. zero scratch
    zero_kernel<<<(NN * CC + 255) / 256, 256>>>();

    // 2. layer 1
    edge1_kernel<<<256, 256>>>(x, ea, src, dst, W1, b1);
    node1_kernel<<<(NN * CC + 255) / 256, 256>>>(x, root1, bias1);

    // 3. layer 2
    edgeH_kernel<<<GRID_EH, 256>>>(h1, ea, src, dst, W2, b2, agg2);
    nodeH_kernel<<<(NN * 32 + 255) / 256, 256>>>(h1, agg2, root2, bias2, h2);

    // 4. layer 3
    edgeH_kernel<<<GRID_EH, 256>>>(h2, ea, src, dst, W3, b3, agg3);
    nodeH_kernel<<<(NN * 32 + 255) / 256, 256>>>(h2, agg3, root3, bias3, h3);

    // 5. CBT all-pairs L1
    dim3 cgrid(NN / 128, NN / 32);
    cbt_kernel<<<cgrid, 128>>>(out);
}

// round 14
// speedup vs baseline: 1.2535x; 1.2535x over previous
#include <cuda_runtime.h>
#include <cstdint>

#define NN 2048
#define EE 65536
#define CC 32
#define TT 64               // edges per CTA tile
#define NTILES (EE / TT)    // 1024

// Packed fp32x2 helpers (sm_103a FFMA2 path — only reachable via PTX)
#define PACK_F32X2(out, lo, hi) \
    asm("mov.b64 %0, {%1, %2};" : "=l"(out) : "f"(lo), "f"(hi))
#define UNPACK_F32X2(lo, hi, in) \
    asm("mov.b64 {%0, %1}, %2;" : "=f"(lo), "=f"(hi) : "l"(in))
#define FMA_F32X2(out, a, b, c) \
    asm("fma.rn.f32x2 %0, %1, %2, %3;" : "=l"(out) : "l"(a), "l"(b), "l"(c))

// Scratch (device globals — no allocation allowed)
__device__ float g_agg1[NN * CC];
__device__ float g_agg2[NN * CC];
__device__ float g_agg3[NN * CC];
__device__ float g_cnt[NN];
__device__ float g_h1[NN * CC];
__device__ float g_h2[NN * CC];
__device__ float g_h3[NN * CC];

// ---------------------------------------------------------------------------
__global__ void zero_kernel() {
    int tid = blockIdx.x * blockDim.x + threadIdx.x;
    if (tid < NN * CC) {
        g_agg1[tid] = 0.f;
        g_agg2[tid] = 0.f;
        g_agg3[tid] = 0.f;
    }
    if (tid < NN) g_cnt[tid] = 0.f;
}

// ---------------------------------------------------------------------------
// Layer 1 edge pass (in_c = 1)
// ---------------------------------------------------------------------------
__global__ void edge1_kernel(const float* __restrict__ x,
                             const float* __restrict__ ea,
                             const int* __restrict__ src,
                             const int* __restrict__ dst,
                             const float* __restrict__ W1,
                             const float* __restrict__ b1) {
    int lane = threadIdx.x & 31;
    int warp = (blockIdx.x * blockDim.x + threadIdx.x) >> 5;
    int nw = (gridDim.x * blockDim.x) >> 5;

    float w[6];
#pragma unroll
    for (int v = 0; v < 6; v++) w[v] = W1[v * CC + lane];
    float bb = b1[lane];

    for (int e = warp; e < EE; e += nw) {
        int s = src[e];
        int d = dst[e];
        float acc = bb;
#pragma unroll
        for (int v = 0; v < 6; v++) acc = fmaf(ea[e * 6 + v], w[v], acc);
        acc = fmaxf(acc, 0.f);
        float msg = x[s] * acc;
        atomicAdd(&g_agg1[d * CC + lane], msg);
        if (lane == 0) atomicAdd(&g_cnt[d], 1.0f);
    }
}

// ---------------------------------------------------------------------------
__global__ void node1_kernel(const float* __restrict__ x,
                             const float* __restrict__ root1,
                             const float* __restrict__ bias1) {
    int tid = blockIdx.x * blockDim.x + threadIdx.x;
    if (tid >= NN * CC) return;
    int n = tid >> 5;
    int o = tid & 31;
    float inv = 1.0f / fmaxf(g_cnt[n], 1.0f);
    float v = g_agg1[tid] * inv + x[n] * root1[o] + bias1[o];
    g_h1[tid] = fmaxf(v, 0.f);
}

// ---------------------------------------------------------------------------
// Heavy edge pass: CTA-cooperative staged tiles of 64 edges (R8 — best known).
// ---------------------------------------------------------------------------
__global__ void __launch_bounds__(256, 2)
edgeH_kernel(const float* __restrict__ h_in,
             const float* __restrict__ ea,
             const int* __restrict__ src,
             const int* __restrict__ dst,
             const float* __restrict__ W,
             const float* __restrict__ b,
             float* __restrict__ agg) {
    int lane = threadIdx.x & 31;
    int w = threadIdx.x >> 5;       // warp in CTA, 0..7
    int q = w & 3;                  // input-channel quarter
    int hh = w >> 2;                // edge half (0/1)
    int ibase = q << 3;

    __shared__ int sh_src[TT];
    __shared__ int sh_dst[TT];
    __shared__ uint64_t sh_ea[TT][6];    // duplicated (v,v) pairs
    __shared__ float sh_h[TT][36];       // padded rows (bank-conflict-free staging)

    // W slice packed: wr2[t][v] = (W[v,ibase+2t,lane], W[v,ibase+2t+1,lane])
    uint64_t wr2[4][6];
#pragma unroll
    for (int t = 0; t < 4; t++)
#pragma unroll
        for (int v = 0; v < 6; v++) {
            float lo = W[v * (CC * CC) + (ibase + 2 * t) * CC + lane];
            float hi = W[v * (CC * CC) + (ibase + 2 * t + 1) * CC + lane];
            PACK_F32X2(wr2[t][v], lo, hi);
        }
    uint64_t bb2[4];
#pragma unroll
    for (int t = 0; t < 4; t++) {
        float lo = b[(ibase + 2 * t) * CC + lane];
        float hi = b[(ibase + 2 * t + 1) * CC + lane];
        PACK_F32X2(bb2[t], lo, hi);
    }

    const float2* ea2 = (const float2*)ea;
    int tx = threadIdx.x;

    for (int tile = blockIdx.x; tile < NTILES; tile += gridDim.x) {
        int e0 = tile * TT;

        // ---- stage A: indices + packed edge attrs ----
        if (tx < TT) {
            sh_src[tx] = src[e0 + tx];
            sh_dst[tx] = dst[e0 + tx];
        }
        if (tx < 192) {
            int e = tx / 3, k = tx % 3;
            float2 v = ea2[(e0 + e) * 3 + k];
            uint64_t p0, p1;
            PACK_F32X2(p0, v.x, v.x);
            PACK_F32X2(p1, v.y, v.y);
            sh_ea[e][2 * k] = p0;
            sh_ea[e][2 * k + 1] = p1;
        }
        __syncthreads();

        // ---- stage B: bulk h gather (independent loads, high MLP) ----
        {
            int e = tx >> 2, qq = tx & 3;
            const float4* hr = (const float4*)(h_in + sh_src[e] * CC);
            float4 hA = __ldg(hr + 2 * qq);
            float4 hB = __ldg(hr + 2 * qq + 1);
            *(float4*)&sh_h[e][qq * 8] = hA;
            *(float4*)&sh_h[e][qq * 8 + 4] = hB;
        }
        __syncthreads();

        // ---- compute: warp (q, hh) handles 32 edges x 8 input channels ----
#pragma unroll 2
        for (int ee = 0; ee < 32; ++ee) {
            int e = hh * 32 + ee;
            uint64_t ep0 = sh_ea[e][0], ep1 = sh_ea[e][1], ep2 = sh_ea[e][2];
            uint64_t ep3 = sh_ea[e][3], ep4 = sh_ea[e][4], ep5 = sh_ea[e][5];
            uint64_t hp0 = *(const uint64_t*)&sh_h[e][ibase + 0];
            uint64_t hp1 = *(const uint64_t*)&sh_h[e][ibase + 2];
            uint64_t hp2 = *(const uint64_t*)&sh_h[e][ibase + 4];
            uint64_t hp3 = *(const uint64_t*)&sh_h[e][ibase + 6];
            int d = sh_dst[e];

            uint64_t mm0 = 0ull, mm1 = 0ull;
#pragma unroll
            for (int t = 0; t < 4; t++) {
                uint64_t acc = bb2[t];
                FMA_F32X2(acc, ep0, wr2[t][0], acc);
                FMA_F32X2(acc, ep1, wr2[t][1], acc);
                FMA_F32X2(acc, ep2, wr2[t][2], acc);
                FMA_F32X2(acc, ep3, wr2[t][3], acc);
                FMA_F32X2(acc, ep4, wr2[t][4], acc);
                FMA_F32X2(acc, ep5, wr2[t][5], acc);
                float w0, w1;
                UNPACK_F32X2(w0, w1, acc);
                w0 = fmaxf(w0, 0.f);
                w1 = fmaxf(w1, 0.f);
                uint64_t accr;
                PACK_F32X2(accr, w0, w1);
                uint64_t hp = (t == 0) ? hp0 : (t == 1) ? hp1 : (t == 2) ? hp2 : hp3;
                if (t & 1) { FMA_F32X2(mm1, hp, accr, mm1); }
                else       { FMA_F32X2(mm0, hp, accr, mm0); }
            }
            float p0, p1, p2, p3;
            UNPACK_F32X2(p0, p1, mm0);
            UNPACK_F32X2(p2, p3, mm1);
            atomicAdd(&agg[d * CC + lane], (p0 + p1) + (p2 + p3));
        }
        __syncthreads();   // protect smem before next tile's stage A
    }
}

// ---------------------------------------------------------------------------
__global__ void nodeH_kernel(const float* __restrict__ h_in,
                             const float* __restrict__ agg,
                             const float* __restrict__ root,
                             const float* __restrict__ bias,
                             float* __restrict__ h_out) {
    int lane = threadIdx.x & 31;
    int warp = (blockIdx.x * blockDim.x + threadIdx.x) >> 5;
    if (warp >= NN) return;

    float r[CC];
#pragma unroll
    for (int i = 0; i < CC; i++) r[i] = root[i * CC + lane];

    float hv = h_in[warp * CC + lane];
    float a0 = bias[lane], a1 = 0.f, a2 = 0.f, a3 = 0.f;
#pragma unroll
    for (int i = 0; i < CC; i += 4) {
        a0 = fmaf(__shfl_sync(0xffffffffu, hv, i + 0), r[i + 0], a0);
        a1 = fmaf(__shfl_sync(0xffffffffu, hv, i + 1), r[i + 1], a1);
        a2 = fmaf(__shfl_sync(0xffffffffu, hv, i + 2), r[i + 2], a2);
        a3 = fmaf(__shfl_sync(0xffffffffu, hv, i + 3), r[i + 3], a3);
    }
    float inv = 1.0f / fmaxf(g_cnt[warp], 1.0f);
    float v = agg[warp * CC + lane] * inv + (a0 + a1) + (a2 + a3);
    h_out[warp * CC + lane] = fmaxf(v, 0.f);
}

// ---------------------------------------------------------------------------
// CBT (symmetric): out[i,j] = out[j,i] = sum_k |h3[j,k] - h3[i,k]|
// 64x64 upper-triangle tiles (ti <= tj). Each block computes once; writes
// the direct tile coalesced and (off-diagonal only) the mirror tile as
// per-thread 4x float4 stores of its 16 consecutive-i results.
// ---------------------------------------------------------------------------
__global__ void __launch_bounds__(256)
cbt_kernel(float* __restrict__ out) {
    int ti = blockIdx.y;
    int tj = blockIdx.x;
    if (tj < ti) return;          // upper triangle only

    __shared__ float si[64 * 33];
    __shared__ float sj[64 * 33];
    int tx = threadIdx.x;
    int i0 = ti * 64;
    int j0 = tj * 64;

    for (int t = tx; t < 64 * CC; t += 256) {
        int r = t >> 5, c = t & 31;
        si[r * 33 + c] = g_h3[(i0 + r) * CC + c];
        sj[r * 33 + c] = g_h3[(j0 + r) * CC + c];
    }
    __syncthreads();

    int j = tx & 63;              // this thread's j column
    int g = tx >> 6;              // i-group (0..3), 16 i's each

    float hj[CC];
#pragma unroll
    for (int k = 0; k < CC; k++) hj[k] = sj[j * 33 + k];

    float c16[16];
#pragma unroll 4
    for (int m = 0; m < 16; m++) {
        const float* sip = &si[(g * 16 + m) * 33];
        float s0 = 0.f, s1 = 0.f;
#pragma unroll
        for (int k = 0; k < CC; k += 2) {
            s0 += fabsf(sip[k] - hj[k]);
            s1 += fabsf(sip[k + 1] - hj[k + 1]);
        }
        c16[m] = s0 + s1;
    }

    // direct tile: row i, coalesced across j
#pragma unroll
    for (int m = 0; m < 16; m++)
        out[(size_t)(i0 + g * 16 + m) * NN + j0 + j] = c16[m];

    // mirror tile (off-diagonal only): row j0+j, 16 consecutive i -> 4x float4
    if (ti != tj) {
        float4* mrow = (float4*)(out + (size_t)(j0 + j) * NN + i0 + g * 16);
#pragma unroll
        for (int m = 0; m < 4; m++)
            mrow[m] = make_float4(c16[4 * m], c16[4 * m + 1],
                                  c16[4 * m + 2], c16[4 * m + 3]);
    }
}

// ---------------------------------------------------------------------------
extern "C" void kernel_launch(void* const* d_in, const int* in_sizes, int n_in,
                              void* d_out, int out_size) {
    const float* x     = (const float*)d_in[0];
    const float* ea    = (const float*)d_in[1];
    const int*   ei    = (const int*)d_in[2];   // int32 (JAX x64 disabled)
    const float* W1    = (const float*)d_in[3];
    const float* b1    = (const float*)d_in[4];
    const float* root1 = (const float*)d_in[5];
    const float* bias1 = (const float*)d_in[6];
    const float* W2    = (const float*)d_in[7];
    const float* b2    = (const float*)d_in[8];
    const float* root2 = (const float*)d_in[9];
    const float* bias2 = (const float*)d_in[10];
    const float* W3    = (const float*)d_in[11];
    const float* b3    = (const float*)d_in[12];
    const float* root3 = (const float*)d_in[13];
    const float* bias3 = (const float*)d_in[14];
    float* out = (float*)d_out;

    const int* src = ei;
    const int* dst = ei + EE;

    float* agg1; float* agg2; float* agg3;
    float* h1;   float* h2;   float* h3;
    cudaGetSymbolAddress((void**)&agg1, g_agg1);
    cudaGetSymbolAddress((void**)&agg2, g_agg2);
    cudaGetSymbolAddress((void**)&agg3, g_agg3);
    cudaGetSymbolAddress((void**)&h1, g_h1);
    cudaGetSymbolAddress((void**)&h2, g_h2);
    cudaGetSymbolAddress((void**)&h3, g_h3);

    // 1. zero scratch
    zero_kernel<<<(NN * CC + 255) / 256, 256>>>();

    // 2. layer 1
    edge1_kernel<<<256, 256>>>(x, ea, src, dst, W1, b1);
    node1_kernel<<<(NN * CC + 255) / 256, 256>>>(x, root1, bias1);

    // 3. layer 2  (296 CTAs = 2 per SM)
    edgeH_kernel<<<296, 256>>>(h1, ea, src, dst, W2, b2, agg2);
    nodeH_kernel<<<(NN * 32 + 255) / 256, 256>>>(h1, agg2, root2, bias2, h2);

    // 4. layer 3
    edgeH_kernel<<<296, 256>>>(h2, ea, src, dst, W3, b3, agg3);
    nodeH_kernel<<<(NN * 32 + 255) / 256, 256>>>(h2, agg3, root3, bias3, h3);

    // 5. CBT all-pairs L1 (symmetric, upper-triangle tiles)
    dim3 cgrid(NN / 64, NN / 64);
    cbt_kernel<<<cgrid, 256>>>(out);
}

// round 15
// speedup vs baseline: 1.2747x; 1.0169x over previous
#include <cuda_runtime.h>
#include <cstdint>

#define NN 2048
#define EE 65536
#define CC 32
#define TT 64               // edges per CTA tile
#define NTILES (EE / TT)    // 1024

// Packed fp32x2 helpers (sm_103a FFMA2 path — only reachable via PTX)
#define PACK_F32X2(out, lo, hi) \
    asm("mov.b64 %0, {%1, %2};" : "=l"(out) : "f"(lo), "f"(hi))
#define UNPACK_F32X2(lo, hi, in) \
    asm("mov.b64 {%0, %1}, %2;" : "=f"(lo), "=f"(hi) : "l"(in))
#define FMA_F32X2(out, a, b, c) \
    asm("fma.rn.f32x2 %0, %1, %2, %3;" : "=l"(out) : "l"(a), "l"(b), "l"(c))

// Scratch (device globals — no allocation allowed)
__device__ float g_agg1[NN * CC];
__device__ float g_agg2[NN * CC];
__device__ float g_agg3[NN * CC];
__device__ float g_cnt[NN];
__device__ float g_h1[NN * CC];
__device__ float g_h2[NN * CC];
__device__ float g_h3[NN * CC];

// ---------------------------------------------------------------------------
__global__ void zero_kernel() {
    int tid = blockIdx.x * blockDim.x + threadIdx.x;
    if (tid < NN * CC) {
        g_agg1[tid] = 0.f;
        g_agg2[tid] = 0.f;
        g_agg3[tid] = 0.f;
    }
    if (tid < NN) g_cnt[tid] = 0.f;
}

// ---------------------------------------------------------------------------
// Layer 1 edge pass (in_c = 1)
// ---------------------------------------------------------------------------
__global__ void edge1_kernel(const float* __restrict__ x,
                             const float* __restrict__ ea,
                             const int* __restrict__ src,
                             const int* __restrict__ dst,
                             const float* __restrict__ W1,
                             const float* __restrict__ b1) {
    int lane = threadIdx.x & 31;
    int warp = (blockIdx.x * blockDim.x + threadIdx.x) >> 5;
    int nw = (gridDim.x * blockDim.x) >> 5;

    float w[6];
#pragma unroll
    for (int v = 0; v < 6; v++) w[v] = W1[v * CC + lane];
    float bb = b1[lane];

    for (int e = warp; e < EE; e += nw) {
        int s = src[e];
        int d = dst[e];
        float acc = bb;
#pragma unroll
        for (int v = 0; v < 6; v++) acc = fmaf(ea[e * 6 + v], w[v], acc);
        acc = fmaxf(acc, 0.f);
        float msg = x[s] * acc;
        atomicAdd(&g_agg1[d * CC + lane], msg);
        if (lane == 0) atomicAdd(&g_cnt[d], 1.0f);
    }
}

// ---------------------------------------------------------------------------
__global__ void node1_kernel(const float* __restrict__ x,
                             const float* __restrict__ root1,
                             const float* __restrict__ bias1) {
    int tid = blockIdx.x * blockDim.x + threadIdx.x;
    if (tid >= NN * CC) return;
    int n = tid >> 5;
    int o = tid & 31;
    float inv = 1.0f / fmaxf(g_cnt[n], 1.0f);
    float v = g_agg1[tid] * inv + x[n] * root1[o] + bias1[o];
    g_h1[tid] = fmaxf(v, 0.f);
}

// ---------------------------------------------------------------------------
// Heavy edge pass: CTA-cooperative staged tile of 64 edges.
// ONE tile per CTA (grid = NTILES) — perfect load balance, no tile loop.
// ---------------------------------------------------------------------------
__global__ void __launch_bounds__(256, 2)
edgeH_kernel(const float* __restrict__ h_in,
             const float* __restrict__ ea,
             const int* __restrict__ src,
             const int* __restrict__ dst,
             const float* __restrict__ W,
             const float* __restrict__ b,
             float* __restrict__ agg) {
    int lane = threadIdx.x & 31;
    int w = threadIdx.x >> 5;       // warp in CTA, 0..7
    int q = w & 3;                  // input-channel quarter
    int hh = w >> 2;                // edge half (0/1)
    int ibase = q << 3;

    __shared__ int sh_src[TT];
    __shared__ int sh_dst[TT];
    __shared__ uint64_t sh_ea[TT][6];    // duplicated (v,v) pairs
    __shared__ float sh_h[TT][36];       // padded rows (bank-conflict-free staging)

    // W slice packed: wr2[t][v] = (W[v,ibase+2t,lane], W[v,ibase+2t+1,lane])
    uint64_t wr2[4][6];
#pragma unroll
    for (int t = 0; t < 4; t++)
#pragma unroll
        for (int v = 0; v < 6; v++) {
            float lo = W[v * (CC * CC) + (ibase + 2 * t) * CC + lane];
            float hi = W[v * (CC * CC) + (ibase + 2 * t + 1) * CC + lane];
            PACK_F32X2(wr2[t][v], lo, hi);
        }
    uint64_t bb2[4];
#pragma unroll
    for (int t = 0; t < 4; t++) {
        float lo = b[(ibase + 2 * t) * CC + lane];
        float hi = b[(ibase + 2 * t + 1) * CC + lane];
        PACK_F32X2(bb2[t], lo, hi);
    }

    const float2* ea2 = (const float2*)ea;
    int tx = threadIdx.x;
    int e0 = blockIdx.x * TT;

    // ---- stage A: indices + packed edge attrs ----
    if (tx < TT) {
        sh_src[tx] = src[e0 + tx];
        sh_dst[tx] = dst[e0 + tx];
    }
    if (tx < 192) {
        int e = tx / 3, k = tx % 3;
        float2 v = ea2[(e0 + e) * 3 + k];
        uint64_t p0, p1;
        PACK_F32X2(p0, v.x, v.x);
        PACK_F32X2(p1, v.y, v.y);
        sh_ea[e][2 * k] = p0;
        sh_ea[e][2 * k + 1] = p1;
    }
    __syncthreads();

    // ---- stage B: bulk h gather (independent loads, high MLP) ----
    {
        int e = tx >> 2, qq = tx & 3;
        const float4* hr = (const float4*)(h_in + sh_src[e] * CC);
        float4 hA = __ldg(hr + 2 * qq);
        float4 hB = __ldg(hr + 2 * qq + 1);
        *(float4*)&sh_h[e][qq * 8] = hA;
        *(float4*)&sh_h[e][qq * 8 + 4] = hB;
    }
    __syncthreads();

    // ---- compute: warp (q, hh) handles 32 edges x 8 input channels ----
#pragma unroll 2
    for (int ee = 0; ee < 32; ++ee) {
        int e = hh * 32 + ee;
        uint64_t ep0 = sh_ea[e][0], ep1 = sh_ea[e][1], ep2 = sh_ea[e][2];
        uint64_t ep3 = sh_ea[e][3], ep4 = sh_ea[e][4], ep5 = sh_ea[e][5];
        uint64_t hp0 = *(const uint64_t*)&sh_h[e][ibase + 0];
        uint64_t hp1 = *(const uint64_t*)&sh_h[e][ibase + 2];
        uint64_t hp2 = *(const uint64_t*)&sh_h[e][ibase + 4];
        uint64_t hp3 = *(const uint64_t*)&sh_h[e][ibase + 6];
        int d = sh_dst[e];

        uint64_t mm0 = 0ull, mm1 = 0ull;
#pragma unroll
        for (int t = 0; t < 4; t++) {
            uint64_t acc = bb2[t];
            FMA_F32X2(acc, ep0, wr2[t][0], acc);
            FMA_F32X2(acc, ep1, wr2[t][1], acc);
            FMA_F32X2(acc, ep2, wr2[t][2], acc);
            FMA_F32X2(acc, ep3, wr2[t][3], acc);
            FMA_F32X2(acc, ep4, wr2[t][4], acc);
            FMA_F32X2(acc, ep5, wr2[t][5], acc);
            float w0, w1;
            UNPACK_F32X2(w0, w1, acc);
            w0 = fmaxf(w0, 0.f);
            w1 = fmaxf(w1, 0.f);
            uint64_t accr;
            PACK_F32X2(accr, w0, w1);
            uint64_t hp = (t == 0) ? hp0 : (t == 1) ? hp1 : (t == 2) ? hp2 : hp3;
            if (t & 1) { FMA_F32X2(mm1, hp, accr, mm1); }
            else       { FMA_F32X2(mm0, hp, accr, mm0); }
        }
        float p0, p1, p2, p3;
        UNPACK_F32X2(p0, p1, mm0);
        UNPACK_F32X2(p2, p3, mm1);
        atomicAdd(&agg[d * CC + lane], (p0 + p1) + (p2 + p3));
    }
}

// ---------------------------------------------------------------------------
__global__ void nodeH_kernel(const float* __restrict__ h_in,
                             const float* __restrict__ agg,
                             const float* __restrict__ root,
                             const float* __restrict__ bias,
                             float* __restrict__ h_out) {
    int lane = threadIdx.x & 31;
    int warp = (blockIdx.x * blockDim.x + threadIdx.x) >> 5;
    if (warp >= NN) return;

    float r[CC];
#pragma unroll
    for (int i = 0; i < CC; i++) r[i] = root[i * CC + lane];

    float hv = h_in[warp * CC + lane];
    float a0 = bias[lane], a1 = 0.f, a2 = 0.f, a3 = 0.f;
#pragma unroll
    for (int i = 0; i < CC; i += 4) {
        a0 = fmaf(__shfl_sync(0xffffffffu, hv, i + 0), r[i + 0], a0);
        a1 = fmaf(__shfl_sync(0xffffffffu, hv, i + 1), r[i + 1], a1);
        a2 = fmaf(__shfl_sync(0xffffffffu, hv, i + 2), r[i + 2], a2);
        a3 = fmaf(__shfl_sync(0xffffffffu, hv, i + 3), r[i + 3], a3);
    }
    float inv = 1.0f / fmaxf(g_cnt[warp], 1.0f);
    float v = agg[warp * CC + lane] * inv + (a0 + a1) + (a2 + a3);
    h_out[warp * CC + lane] = fmaxf(v, 0.f);
}

// ---------------------------------------------------------------------------
// CBT (symmetric): out[i,j] = out[j,i] = sum_k |h3[j,k] - h3[i,k]|
// 64x64 upper-triangle tiles; direct write coalesced + mirrored float4 rows.
// ---------------------------------------------------------------------------
__global__ void __launch_bounds__(256)
cbt_kernel(float* __restrict__ out) {
    int ti = blockIdx.y;
    int tj = blockIdx.x;
    if (tj < ti) return;          // upper triangle only

    __shared__ float si[64 * 33];
    __shared__ float sj[64 * 33];
    int tx = threadIdx.x;
    int i0 = ti * 64;
    int j0 = tj * 64;

    for (int t = tx; t < 64 * CC; t += 256) {
        int r = t >> 5, c = t & 31;
        si[r * 33 + c] = g_h3[(i0 + r) * CC + c];
        sj[r * 33 + c] = g_h3[(j0 + r) * CC + c];
    }
    __syncthreads();

    int j = tx & 63;              // this thread's j column
    int g = tx >> 6;              // i-group (0..3), 16 i's each

    float hj[CC];
#pragma unroll
    for (int k = 0; k < CC; k++) hj[k] = sj[j * 33 + k];

    float c16[16];
#pragma unroll 4
    for (int m = 0; m < 16; m++) {
        const float* sip = &si[(g * 16 + m) * 33];
        float s0 = 0.f, s1 = 0.f;
#pragma unroll
        for (int k = 0; k < CC; k += 2) {
            s0 += fabsf(sip[k] - hj[k]);
            s1 += fabsf(sip[k + 1] - hj[k + 1]);
        }
        c16[m] = s0 + s1;
    }

    // direct tile: row i, coalesced across j
#pragma unroll
    for (int m = 0; m < 16; m++)
        out[(size_t)(i0 + g * 16 + m) * NN + j0 + j] = c16[m];

    // mirror tile (off-diagonal only): row j0+j, 16 consecutive i -> 4x float4
    if (ti != tj) {
        float4* mrow = (float4*)(out + (size_t)(j0 + j) * NN + i0 + g * 16);
#pragma unroll
        for (int m = 0; m < 4; m++)
            mrow[m] = make_float4(c16[4 * m], c16[4 * m + 1],
                                  c16[4 * m + 2], c16[4 * m + 3]);
    }
}

// ---------------------------------------------------------------------------
extern "C" void kernel_launch(void* const* d_in, const int* in_sizes, int n_in,
                              void* d_out, int out_size) {
    const float* x     = (const float*)d_in[0];
    const float* ea    = (const float*)d_in[1];
    const int*   ei    = (const int*)d_in[2];   // int32 (JAX x64 disabled)
    const float* W1    = (const float*)d_in[3];
    const float* b1    = (const float*)d_in[4];
    const float* root1 = (const float*)d_in[5];
    const float* bias1 = (const float*)d_in[6];
    const float* W2    = (const float*)d_in[7];
    const float* b2    = (const float*)d_in[8];
    const float* root2 = (const float*)d_in[9];
    const float* bias2 = (const float*)d_in[10];
    const float* W3    = (const float*)d_in[11];
    const float* b3    = (const float*)d_in[12];
    const float* root3 = (const float*)d_in[13];
    const float* bias3 = (const float*)d_in[14];
    float* out = (float*)d_out;

    const int* src = ei;
    const int* dst = ei + EE;

    float* agg1; float* agg2; float* agg3;
    float* h1;   float* h2;   float* h3;
    cudaGetSymbolAddress((void**)&agg1, g_agg1);
    cudaGetSymbolAddress((void**)&agg2, g_agg2);
    cudaGetSymbolAddress((void**)&agg3, g_agg3);
    cudaGetSymbolAddress((void**)&h1, g_h1);
    cudaGetSymbolAddress((void**)&h2, g_h2);
    cudaGetSymbolAddress((void**)&h3, g_h3);

    // 1. zero scratch
    zero_kernel<<<(NN * CC + 255) / 256, 256>>>();

    // 2. layer 1
    edge1_kernel<<<256, 256>>>(x, ea, src, dst, W1, b1);
    node1_kernel<<<(NN * CC + 255) / 256, 256>>>(x, root1, bias1);

    // 3. layer 2  (1024 CTAs — one 64-edge tile each)
    edgeH_kernel<<<NTILES, 256>>>(h1, ea, src, dst, W2, b2, agg2);
    nodeH_kernel<<<(NN * 32 + 255) / 256, 256>>>(h1, agg2, root2, bias2, h2);

    // 4. layer 3
    edgeH_kernel<<<NTILES, 256>>>(h2, ea, src, dst, W3, b3, agg3);
    nodeH_kernel<<<(NN * 32 + 255) / 256, 256>>>(h2, agg3, root3, bias3, h3);

    // 5. CBT all-pairs L1 (symmetric, upper-triangle tiles)
    dim3 cgrid(NN / 64, NN / 64);
    cbt_kernel<<<cgrid, 256>>>(out);
}